// round 1
// baseline (speedup 1.0000x reference)
#include <cuda_runtime.h>

#define H_     4
#define F_     32
#define HF_    128
#define FIN_   128
#define EDGED_ 64
#define HID_   256
#define BMAX_  64
#define NMAX_  96000
#define EMAX_  600000

// ---------------- scratch (device globals; no allocation allowed) ----------
__device__ float    g_proj[NMAX_ * HF_];
__device__ float    g_acc_src[NMAX_ * HF_];
__device__ float    g_acc_trg[NMAX_ * HF_];
__device__ float    g_ss[NMAX_ * H_];
__device__ float    g_st[NMAX_ * H_];
__device__ float    g_scores[EMAX_ * H_];       // scores, later overwritten with exp()
__device__ float    g_den_src[NMAX_ * H_];
__device__ float    g_den_trg[NMAX_ * H_];
__device__ float    g_asb[BMAX_ * HF_];         // a_src * src_bridge per batch
__device__ float    g_atb[BMAX_ * HF_];         // a_trg * trg_bridge per batch
__device__ float    g_wae[BMAX_ * EDGED_ * H_]; // folded W_edge*(a_edge*edge_bridge): [b][d][h]
__device__ unsigned g_gmax;                     // order-preserving encoded float max

// ordered-uint encoding of float (monotone)
__device__ __forceinline__ unsigned encf(float f) {
    unsigned u = __float_as_uint(f);
    return (u & 0x80000000u) ? ~u : (u | 0x80000000u);
}
__device__ __forceinline__ float decf(unsigned u) {
    return (u & 0x80000000u) ? __uint_as_float(u ^ 0x80000000u) : __uint_as_float(~u);
}

// ---------------- K_init: zero denominators, reset global max --------------
__global__ void k_init(int N) {
    int i = blockIdx.x * blockDim.x + threadIdx.x;
    if (i == 0) g_gmax = 0u;   // 0 < encf(any float)
    if (i < N * H_) { g_den_src[i] = 0.f; g_den_trg[i] = 0.f; }
}

// ---------------- K0: per-batch instruction bridges + folded edge matrix ---
__global__ __launch_bounds__(128) void k0_batch(
    const float* __restrict__ ins,
    const float* __restrict__ Wsi, const float* __restrict__ bsi,
    const float* __restrict__ Wti, const float* __restrict__ bti,
    const float* __restrict__ Wei, const float* __restrict__ bei,
    const float* __restrict__ a_src, const float* __restrict__ a_trg,
    const float* __restrict__ a_edge, const float* __restrict__ W_edge)
{
    __shared__ float si[HID_];
    __shared__ float aeb[HF_];
    int b = blockIdx.x, t = threadIdx.x;
    si[t] = ins[b * HID_ + t];
    si[t + 128] = ins[b * HID_ + t + 128];
    __syncthreads();

    float s1 = bsi[t], s2 = bti[t], s3 = bei[t];
    #pragma unroll 4
    for (int k = 0; k < HID_; k++) {
        float iv = si[k];
        s1 += iv * Wsi[k * HF_ + t];
        s2 += iv * Wti[k * HF_ + t];
        s3 += iv * Wei[k * HF_ + t];
    }
    g_asb[b * HF_ + t] = a_src[t] * s1;
    g_atb[b * HF_ + t] = a_trg[t] * s2;
    aeb[t] = a_edge[t] * s3;
    __syncthreads();

    // wae[b][d][h] = sum_f W_edge[d, h*32+f] * aeb[h*32+f]
    #pragma unroll
    for (int r = 0; r < 2; r++) {
        int idx = t + r * 128;
        int d = idx >> 2, h = idx & 3;
        float w = 0.f;
        #pragma unroll
        for (int f = 0; f < F_; f++) w += W_edge[d * HF_ + h * F_ + f] * aeb[h * F_ + f];
        g_wae[b * (EDGED_ * H_) + idx] = w;
    }
}

// ---------------- K1: fused GEMM  x @ [W_proj | W_skip] --------------------
// 128x128 tile per block, BK=8, 256 threads, 8x8 microtile.
// blockIdx.y==0 -> proj; ==1 -> skip (+bias) written to BOTH accumulators.
__global__ __launch_bounds__(256) void k1_gemm(
    const float* __restrict__ x, const float* __restrict__ Wp,
    const float* __restrict__ Wsk, const float* __restrict__ bias, int N)
{
    __shared__ float As[8][128];
    __shared__ float Bs[8][128];
    const float* W = (blockIdx.y == 0) ? Wp : Wsk;
    int t = threadIdx.x;
    int row0 = blockIdx.x * 128;
    int tx = t & 15, ty = t >> 4;

    float acc[8][8];
    #pragma unroll
    for (int i = 0; i < 8; i++)
        #pragma unroll
        for (int j = 0; j < 8; j++) acc[i][j] = 0.f;

    int lr = t >> 1, lq = t & 1;          // A tile: row lr, float4 quad lq
    int bk = t >> 5, bc = (t & 31) * 4;   // B tile

    for (int k0 = 0; k0 < FIN_; k0 += 8) {
        int arow = row0 + lr;
        float4 av = make_float4(0.f, 0.f, 0.f, 0.f);
        if (arow < N) av = *(const float4*)(x + (size_t)arow * FIN_ + k0 + lq * 4);
        As[lq * 4 + 0][lr] = av.x; As[lq * 4 + 1][lr] = av.y;
        As[lq * 4 + 2][lr] = av.z; As[lq * 4 + 3][lr] = av.w;
        float4 bv = *(const float4*)(W + (size_t)(k0 + bk) * HF_ + bc);
        *(float4*)(&Bs[bk][bc]) = bv;
        __syncthreads();

        #pragma unroll
        for (int kk = 0; kk < 8; kk++) {
            float4 a0 = *(float4*)(&As[kk][ty * 8]);
            float4 a1 = *(float4*)(&As[kk][ty * 8 + 4]);
            float4 b0 = *(float4*)(&Bs[kk][tx * 8]);
            float4 b1 = *(float4*)(&Bs[kk][tx * 8 + 4]);
            float a[8] = {a0.x, a0.y, a0.z, a0.w, a1.x, a1.y, a1.z, a1.w};
            float b[8] = {b0.x, b0.y, b0.z, b0.w, b1.x, b1.y, b1.z, b1.w};
            #pragma unroll
            for (int i = 0; i < 8; i++)
                #pragma unroll
                for (int j = 0; j < 8; j++) acc[i][j] += a[i] * b[j];
        }
        __syncthreads();
    }

    if (blockIdx.y == 0) {
        #pragma unroll
        for (int i = 0; i < 8; i++) {
            int row = row0 + ty * 8 + i;
            if (row >= N) break;
            float4 v0 = make_float4(acc[i][0], acc[i][1], acc[i][2], acc[i][3]);
            float4 v1 = make_float4(acc[i][4], acc[i][5], acc[i][6], acc[i][7]);
            *(float4*)(g_proj + (size_t)row * HF_ + tx * 8) = v0;
            *(float4*)(g_proj + (size_t)row * HF_ + tx * 8 + 4) = v1;
        }
    } else {
        float4 bb0 = *(const float4*)(bias + tx * 8);
        float4 bb1 = *(const float4*)(bias + tx * 8 + 4);
        #pragma unroll
        for (int i = 0; i < 8; i++) {
            int row = row0 + ty * 8 + i;
            if (row >= N) break;
            float4 v0 = make_float4(acc[i][0] + bb0.x, acc[i][1] + bb0.y,
                                    acc[i][2] + bb0.z, acc[i][3] + bb0.w);
            float4 v1 = make_float4(acc[i][4] + bb1.x, acc[i][5] + bb1.y,
                                    acc[i][6] + bb1.z, acc[i][7] + bb1.w);
            *(float4*)(g_acc_src + (size_t)row * HF_ + tx * 8) = v0;
            *(float4*)(g_acc_src + (size_t)row * HF_ + tx * 8 + 4) = v1;
            *(float4*)(g_acc_trg + (size_t)row * HF_ + tx * 8) = v0;
            *(float4*)(g_acc_trg + (size_t)row * HF_ + tx * 8 + 4) = v1;
        }
    }
}

// ---------------- K1b: per-node source/target scores -----------------------
__global__ __launch_bounds__(256) void k1b_node_scores(int N, int mle) {
    int warp = (blockIdx.x * blockDim.x + threadIdx.x) >> 5;
    int lane = threadIdx.x & 31;
    if (warp >= N) return;
    int n = warp;
    int b = n / mle;
    int c = lane * 4, h = lane >> 3;
    float4 p = *(const float4*)(g_proj + (size_t)n * HF_ + c);
    float4 a = *(const float4*)(g_asb + b * HF_ + c);
    float v = p.x * a.x + p.y * a.y + p.z * a.z + p.w * a.w;
    v += __shfl_xor_sync(~0u, v, 1);
    v += __shfl_xor_sync(~0u, v, 2);
    v += __shfl_xor_sync(~0u, v, 4);
    if ((lane & 7) == 0) g_ss[n * H_ + h] = v;
    float4 a2 = *(const float4*)(g_atb + b * HF_ + c);
    float w = p.x * a2.x + p.y * a2.y + p.z * a2.z + p.w * a2.w;
    w += __shfl_xor_sync(~0u, w, 1);
    w += __shfl_xor_sync(~0u, w, 2);
    w += __shfl_xor_sync(~0u, w, 4);
    if ((lane & 7) == 0) g_st[n * H_ + h] = w;
}

// ---------------- K2: per-edge scores + block-reduced global max -----------
__global__ __launch_bounds__(256) void k2_edge_scores(
    const int* __restrict__ ei, const float* __restrict__ edges,
    const int* __restrict__ bids, int E)
{
    int t = threadIdx.x;
    int e = blockIdx.x * 32 + (t >> 3);
    int j = t & 7;
    float m = -3.402823e38f;
    if (e < E) {
        int src = ei[e], trg = ei[E + e], b = bids[e];
        const float4* ep = (const float4*)(edges + (size_t)e * EDGED_);
        float4 e0 = ep[j * 2], e1 = ep[j * 2 + 1];
        float ev[8] = {e0.x, e0.y, e0.z, e0.w, e1.x, e1.y, e1.z, e1.w};
        const float4* wb = (const float4*)(g_wae + b * (EDGED_ * H_) + j * 32);
        float4 acc = make_float4(0.f, 0.f, 0.f, 0.f);
        #pragma unroll
        for (int i = 0; i < 8; i++) {
            float4 w = wb[i];
            acc.x += ev[i] * w.x; acc.y += ev[i] * w.y;
            acc.z += ev[i] * w.z; acc.w += ev[i] * w.w;
        }
        #pragma unroll
        for (int mask = 1; mask <= 4; mask <<= 1) {
            acc.x += __shfl_xor_sync(~0u, acc.x, mask);
            acc.y += __shfl_xor_sync(~0u, acc.y, mask);
            acc.z += __shfl_xor_sync(~0u, acc.z, mask);
            acc.w += __shfl_xor_sync(~0u, acc.w, mask);
        }
        if (j == 0) {
            float4 sv = *(const float4*)(g_ss + src * H_);
            float4 tv = *(const float4*)(g_st + trg * H_);
            float4 s = make_float4(acc.x + sv.x + tv.x, acc.y + sv.y + tv.y,
                                   acc.z + sv.z + tv.z, acc.w + sv.w + tv.w);
            s.x = s.x > 0.f ? s.x : 0.2f * s.x;
            s.y = s.y > 0.f ? s.y : 0.2f * s.y;
            s.z = s.z > 0.f ? s.z : 0.2f * s.z;
            s.w = s.w > 0.f ? s.w : 0.2f * s.w;
            *((float4*)g_scores + e) = s;
            m = fmaxf(fmaxf(s.x, s.y), fmaxf(s.z, s.w));
        }
    }
    // block max reduction, one atomic per block
    __shared__ float wm[8];
    #pragma unroll
    for (int mask = 16; mask >= 1; mask >>= 1) m = fmaxf(m, __shfl_xor_sync(~0u, m, mask));
    if ((t & 31) == 0) wm[t >> 5] = m;
    __syncthreads();
    if (t < 8) {
        float v = wm[t];
        v = fmaxf(v, __shfl_xor_sync(0xffu, v, 4));
        v = fmaxf(v, __shfl_xor_sync(0xffu, v, 2));
        v = fmaxf(v, __shfl_xor_sync(0xffu, v, 1));
        if (t == 0) atomicMax(&g_gmax, encf(v));
    }
}

// ---------------- K3a: exp(score - max), denominators via float4 RED -------
__global__ void k3a_exp_denom(const int* __restrict__ ei, int E) {
    int e = blockIdx.x * blockDim.x + threadIdx.x;
    if (e >= E) return;
    float gm = decf(g_gmax);
    float4 s = *((float4*)g_scores + e);
    float4 ex = make_float4(expf(s.x - gm), expf(s.y - gm), expf(s.z - gm), expf(s.w - gm));
    *((float4*)g_scores + e) = ex;
    int src = ei[e], trg = ei[E + e];
    atomicAdd((float4*)(g_den_trg + trg * H_), ex);
    atomicAdd((float4*)(g_den_src + src * H_), ex);
}

// ---------------- K3inv: invert denominators once ---------------------------
__global__ void k3inv(int N) {
    int i = blockIdx.x * blockDim.x + threadIdx.x;
    if (i >= N * H_) return;
    g_den_src[i] = 1.f / (g_den_src[i] + 1e-16f);
    g_den_trg[i] = 1.f / (g_den_trg[i] + 1e-16f);
}

// ---------------- K3b: weighted scatter (warp per edge, float4 RED) --------
__global__ __launch_bounds__(256) void k3b_scatter(const int* __restrict__ ei, int E) {
    int e = (int)((blockIdx.x * 256 + threadIdx.x) >> 5);
    int lane = threadIdx.x & 31;
    if (e >= E) return;
    int src = ei[e], trg = ei[E + e];
    int h = lane >> 3;
    float ex = g_scores[e * H_ + h];
    float at = ex * g_den_trg[trg * H_ + h];   // attention toward trg branch
    float as = ex * g_den_src[src * H_ + h];   // attention toward src branch
    float4 ps = *((const float4*)g_proj + (size_t)src * 32 + lane);
    float4 pt = *((const float4*)g_proj + (size_t)trg * 32 + lane);
    float4 vt = make_float4(ps.x * at, ps.y * at, ps.z * at, ps.w * at);
    float4 vs = make_float4(pt.x * as, pt.y * as, pt.z * as, pt.w * as);
    atomicAdd((float4*)g_acc_trg + (size_t)trg * 32 + lane, vt);
    atomicAdd((float4*)g_acc_src + (size_t)src * 32 + lane, vs);
}

// ---------------- K4: concat + LayerNorm (warp per node) -------------------
__global__ __launch_bounds__(256) void k4_layernorm(
    const float* __restrict__ gamma, const float* __restrict__ beta,
    float* __restrict__ out, int N)
{
    int n = (int)((blockIdx.x * 256 + threadIdx.x) >> 5);
    int lane = threadIdx.x & 31;
    if (n >= N) return;
    float4 a = *((const float4*)g_acc_src + (size_t)n * 32 + lane);
    float4 b = *((const float4*)g_acc_trg + (size_t)n * 32 + lane);
    float s = a.x + a.y + a.z + a.w + b.x + b.y + b.z + b.w;
    float q = a.x * a.x + a.y * a.y + a.z * a.z + a.w * a.w +
              b.x * b.x + b.y * b.y + b.z * b.z + b.w * b.w;
    #pragma unroll
    for (int mask = 16; mask >= 1; mask >>= 1) {
        s += __shfl_xor_sync(~0u, s, mask);
        q += __shfl_xor_sync(~0u, q, mask);
    }
    float mu = s * (1.f / 256.f);
    float var = q * (1.f / 256.f) - mu * mu;
    float r = rsqrtf(var + 1e-5f);
    float4 g1 = ((const float4*)gamma)[lane];
    float4 be1 = ((const float4*)beta)[lane];
    float4 g2 = ((const float4*)gamma)[32 + lane];
    float4 be2 = ((const float4*)beta)[32 + lane];
    float4 o1 = make_float4((a.x - mu) * r * g1.x + be1.x, (a.y - mu) * r * g1.y + be1.y,
                            (a.z - mu) * r * g1.z + be1.z, (a.w - mu) * r * g1.w + be1.w);
    float4 o2 = make_float4((b.x - mu) * r * g2.x + be2.x, (b.y - mu) * r * g2.y + be2.y,
                            (b.z - mu) * r * g2.z + be2.z, (b.w - mu) * r * g2.w + be2.w);
    ((float4*)out)[(size_t)n * 64 + lane] = o1;
    ((float4*)out)[(size_t)n * 64 + 32 + lane] = o2;
}

// ---------------------------------------------------------------------------
static inline int cdiv(int a, int b) { return (a + b - 1) / b; }

extern "C" void kernel_launch(void* const* d_in, const int* in_sizes, int n_in,
                              void* d_out, int out_size)
{
    const float* x      = (const float*)d_in[0];
    const int*   ei     = (const int*)d_in[1];
    const float* edges  = (const float*)d_in[2];
    const float* ins    = (const float*)d_in[3];
    const int*   bids   = (const int*)d_in[4];
    // d_in[5] = max_local_entity (derived as N/B below, no device read needed)
    const float* Wp     = (const float*)d_in[6];
    const float* We     = (const float*)d_in[7];
    const float* Wsi    = (const float*)d_in[8];
    const float* bsi    = (const float*)d_in[9];
    const float* Wti    = (const float*)d_in[10];
    const float* bti    = (const float*)d_in[11];
    const float* Wei    = (const float*)d_in[12];
    const float* bei    = (const float*)d_in[13];
    const float* a_src  = (const float*)d_in[14];
    const float* a_trg  = (const float*)d_in[15];
    const float* a_edge = (const float*)d_in[16];
    const float* bias   = (const float*)d_in[17];
    const float* Wsk    = (const float*)d_in[18];
    const float* gamma  = (const float*)d_in[19];
    const float* beta   = (const float*)d_in[20];

    int N = in_sizes[0] / FIN_;
    int E = in_sizes[2] / EDGED_;
    int B = in_sizes[3] / HID_;
    int mle = N / B;

    k_init<<<cdiv(N * H_, 256), 256>>>(N);
    k0_batch<<<B, 128>>>(ins, Wsi, bsi, Wti, bti, Wei, bei, a_src, a_trg, a_edge, We);
    {
        dim3 grid(cdiv(N, 128), 2);
        k1_gemm<<<grid, 256>>>(x, Wp, Wsk, bias, N);
    }
    k1b_node_scores<<<cdiv(N * 32, 256), 256>>>(N, mle);
    k2_edge_scores<<<cdiv(E, 32), 256>>>(ei, edges, bids, E);
    k3a_exp_denom<<<cdiv(E, 256), 256>>>(ei, E);
    k3inv<<<cdiv(N * H_, 256), 256>>>(N);
    k3b_scatter<<<cdiv(E * 32, 256), 256>>>(ei, E);
    k4_layernorm<<<cdiv(N * 32, 256), 256>>>(gamma, beta, (float*)d_out, N);
}

// round 2
// speedup vs baseline: 1.0392x; 1.0392x over previous
#include <cuda_runtime.h>

#define H_     4
#define F_     32
#define HF_    128
#define FIN_   128
#define EDGED_ 64
#define HID_   256
#define BMAX_  64
#define NMAX_  96000
#define EMAX_  600000

// ---------------- scratch (device globals; no allocation allowed) ----------
__device__ float    g_proj[NMAX_ * HF_];
__device__ float    g_acc_src[NMAX_ * HF_];
__device__ float    g_acc_trg[NMAX_ * HF_];
__device__ float    g_ss[NMAX_ * H_];
__device__ float    g_st[NMAX_ * H_];
__device__ float    g_scores[EMAX_ * H_];       // scores, later overwritten with exp()
__device__ float    g_den_src[NMAX_ * H_];
__device__ float    g_den_trg[NMAX_ * H_];
__device__ float    g_asb[BMAX_ * HF_];         // a_src * src_bridge per batch
__device__ float    g_atb[BMAX_ * HF_];         // a_trg * trg_bridge per batch
__device__ float    g_wae[BMAX_ * EDGED_ * H_]; // folded W_edge*(a_edge*edge_bridge): [b][d][h]
__device__ unsigned g_gmax;                     // order-preserving encoded float max

// ordered-uint encoding of float (monotone)
__device__ __forceinline__ unsigned encf(float f) {
    unsigned u = __float_as_uint(f);
    return (u & 0x80000000u) ? ~u : (u | 0x80000000u);
}
__device__ __forceinline__ float decf(unsigned u) {
    return (u & 0x80000000u) ? __uint_as_float(u ^ 0x80000000u) : __uint_as_float(~u);
}

// ---- packed f32x2 helpers (sm_103a FFMA2 path, PTX-only) -------------------
__device__ __forceinline__ unsigned long long packff(float x, float y) {
    unsigned long long r;
    asm("mov.b64 %0, {%1, %2};" : "=l"(r) : "f"(x), "f"(y));
    return r;
}
__device__ __forceinline__ unsigned long long packdup(float x) {
    unsigned long long r;
    asm("mov.b64 %0, {%1, %1};" : "=l"(r) : "f"(x));
    return r;
}
__device__ __forceinline__ float2 unpk(unsigned long long v) {
    float2 r;
    asm("mov.b64 {%0, %1}, %2;" : "=f"(r.x), "=f"(r.y) : "l"(v));
    return r;
}
__device__ __forceinline__ void fma2(unsigned long long& acc, unsigned long long a,
                                     unsigned long long b) {
    asm("fma.rn.f32x2 %0, %1, %2, %0;" : "+l"(acc) : "l"(a), "l"(b));
}
__device__ __forceinline__ unsigned long long add2(unsigned long long a,
                                                   unsigned long long b) {
    unsigned long long r;
    asm("add.rn.f32x2 %0, %1, %2;" : "=l"(r) : "l"(a), "l"(b));
    return r;
}

// ---------------- K_init: zero denominators, reset global max --------------
__global__ void k_init(int N) {
    int i = blockIdx.x * blockDim.x + threadIdx.x;
    if (i == 0) g_gmax = 0u;   // 0 < encf(any float)
    if (i < N * H_) { g_den_src[i] = 0.f; g_den_trg[i] = 0.f; }
}

// ---------------- K0: per-batch instruction bridges + folded edge matrix ---
__global__ __launch_bounds__(128) void k0_batch(
    const float* __restrict__ ins,
    const float* __restrict__ Wsi, const float* __restrict__ bsi,
    const float* __restrict__ Wti, const float* __restrict__ bti,
    const float* __restrict__ Wei, const float* __restrict__ bei,
    const float* __restrict__ a_src, const float* __restrict__ a_trg,
    const float* __restrict__ a_edge, const float* __restrict__ W_edge)
{
    __shared__ float si[HID_];
    __shared__ float aeb[HF_];
    int b = blockIdx.x, t = threadIdx.x;
    si[t] = ins[b * HID_ + t];
    si[t + 128] = ins[b * HID_ + t + 128];
    __syncthreads();

    float s1 = bsi[t], s2 = bti[t], s3 = bei[t];
    #pragma unroll 4
    for (int k = 0; k < HID_; k++) {
        float iv = si[k];
        s1 += iv * Wsi[k * HF_ + t];
        s2 += iv * Wti[k * HF_ + t];
        s3 += iv * Wei[k * HF_ + t];
    }
    g_asb[b * HF_ + t] = a_src[t] * s1;
    g_atb[b * HF_ + t] = a_trg[t] * s2;
    aeb[t] = a_edge[t] * s3;
    __syncthreads();

    // wae[b][d][h] = sum_f W_edge[d, h*32+f] * aeb[h*32+f]
    #pragma unroll
    for (int r = 0; r < 2; r++) {
        int idx = t + r * 128;
        int d = idx >> 2, h = idx & 3;
        float w = 0.f;
        #pragma unroll
        for (int f = 0; f < F_; f++) w += W_edge[d * HF_ + h * F_ + f] * aeb[h * F_ + f];
        g_wae[b * (EDGED_ * H_) + idx] = w;
    }
}

// ---------------- K1: fused GEMM  x @ [W_proj | W_skip], FFMA2 mainloop ----
// 128x128 tile per block, BK=8, 256 threads, 8x8 microtile as 8x(4 f32x2).
// blockIdx.y==0 -> proj + fused node scores; ==1 -> skip(+bias) to both accs.
__global__ __launch_bounds__(256) void k1_gemm(
    const float* __restrict__ x, const float* __restrict__ Wp,
    const float* __restrict__ Wsk, const float* __restrict__ bias,
    int N, int mle)
{
    __shared__ float As[8][128];
    __shared__ float Bs[8][128];
    const float* W = (blockIdx.y == 0) ? Wp : Wsk;
    int t = threadIdx.x;
    int row0 = blockIdx.x * 128;
    int tx = t & 15, ty = t >> 4;

    unsigned long long acc2[8][4];
    #pragma unroll
    for (int i = 0; i < 8; i++)
        #pragma unroll
        for (int j = 0; j < 4; j++) acc2[i][j] = 0ull;

    int lr = t >> 1, lq = t & 1;          // A tile: row lr, float4 quad lq
    int bk = t >> 5, bc = (t & 31) * 4;   // B tile

    for (int k0 = 0; k0 < FIN_; k0 += 8) {
        int arow = row0 + lr;
        float4 av = make_float4(0.f, 0.f, 0.f, 0.f);
        if (arow < N) av = *(const float4*)(x + (size_t)arow * FIN_ + k0 + lq * 4);
        As[lq * 4 + 0][lr] = av.x; As[lq * 4 + 1][lr] = av.y;
        As[lq * 4 + 2][lr] = av.z; As[lq * 4 + 3][lr] = av.w;
        float4 bv = *(const float4*)(W + (size_t)(k0 + bk) * HF_ + bc);
        *(float4*)(&Bs[bk][bc]) = bv;
        __syncthreads();

        #pragma unroll
        for (int kk = 0; kk < 8; kk++) {
            float4 a0 = *(float4*)(&As[kk][ty * 8]);
            float4 a1 = *(float4*)(&As[kk][ty * 8 + 4]);
            ulonglong2 bp0 = *(const ulonglong2*)(&Bs[kk][tx * 8]);
            ulonglong2 bp1 = *(const ulonglong2*)(&Bs[kk][tx * 8 + 4]);
            unsigned long long bb[4] = {bp0.x, bp0.y, bp1.x, bp1.y};
            float a[8] = {a0.x, a0.y, a0.z, a0.w, a1.x, a1.y, a1.z, a1.w};
            #pragma unroll
            for (int i = 0; i < 8; i++) {
                unsigned long long aa = packdup(a[i]);
                fma2(acc2[i][0], aa, bb[0]);
                fma2(acc2[i][1], aa, bb[1]);
                fma2(acc2[i][2], aa, bb[2]);
                fma2(acc2[i][3], aa, bb[3]);
            }
        }
        __syncthreads();
    }

    if (blockIdx.y == 0) {
        // proj store + fused node-score partials.
        // cols covered by this thread: tx*8 .. tx*8+7, all inside head (tx>>2).
        int head = tx >> 2;
        #pragma unroll
        for (int i = 0; i < 8; i++) {
            int row = row0 + ty * 8 + i;
            int rc = row < N ? row : N - 1;
            int b = rc / mle;
            float2 c0 = unpk(acc2[i][0]);
            float2 c1 = unpk(acc2[i][1]);
            float2 c2 = unpk(acc2[i][2]);
            float2 c3 = unpk(acc2[i][3]);
            if (row < N) {
                float4 v0 = make_float4(c0.x, c0.y, c1.x, c1.y);
                float4 v1 = make_float4(c2.x, c2.y, c3.x, c3.y);
                *(float4*)(g_proj + (size_t)row * HF_ + tx * 8) = v0;
                *(float4*)(g_proj + (size_t)row * HF_ + tx * 8 + 4) = v1;
            }
            const float4* ab = (const float4*)(g_asb + b * HF_ + tx * 8);
            const float4* tb = (const float4*)(g_atb + b * HF_ + tx * 8);
            float4 ab0 = ab[0], ab1 = ab[1];
            float4 tb0 = tb[0], tb1 = tb[1];
            float s = c0.x * ab0.x + c0.y * ab0.y + c1.x * ab0.z + c1.y * ab0.w
                    + c2.x * ab1.x + c2.y * ab1.y + c3.x * ab1.z + c3.y * ab1.w;
            float u = c0.x * tb0.x + c0.y * tb0.y + c1.x * tb0.z + c1.y * tb0.w
                    + c2.x * tb1.x + c2.y * tb1.y + c3.x * tb1.z + c3.y * tb1.w;
            // reduce across the 4 consecutive lanes of this head group
            s += __shfl_xor_sync(~0u, s, 1);
            s += __shfl_xor_sync(~0u, s, 2);
            u += __shfl_xor_sync(~0u, u, 1);
            u += __shfl_xor_sync(~0u, u, 2);
            if ((tx & 3) == 0 && row < N) {
                g_ss[row * H_ + head] = s;
                g_st[row * H_ + head] = u;
            }
        }
    } else {
        const ulonglong2* bp = (const ulonglong2*)(bias + tx * 8);
        ulonglong2 bq0 = bp[0], bq1 = bp[1];
        unsigned long long bpk[4] = {bq0.x, bq0.y, bq1.x, bq1.y};
        #pragma unroll
        for (int i = 0; i < 8; i++) {
            int row = row0 + ty * 8 + i;
            if (row >= N) break;
            ulonglong2 w0, w1;
            w0.x = add2(acc2[i][0], bpk[0]);
            w0.y = add2(acc2[i][1], bpk[1]);
            w1.x = add2(acc2[i][2], bpk[2]);
            w1.y = add2(acc2[i][3], bpk[3]);
            *(ulonglong2*)(g_acc_src + (size_t)row * HF_ + tx * 8) = w0;
            *(ulonglong2*)(g_acc_src + (size_t)row * HF_ + tx * 8 + 4) = w1;
            *(ulonglong2*)(g_acc_trg + (size_t)row * HF_ + tx * 8) = w0;
            *(ulonglong2*)(g_acc_trg + (size_t)row * HF_ + tx * 8 + 4) = w1;
        }
    }
}

// ---------------- K2: per-edge scores + block-reduced global max -----------
__global__ __launch_bounds__(256) void k2_edge_scores(
    const int* __restrict__ ei, const float* __restrict__ edges,
    const int* __restrict__ bids, int E)
{
    int t = threadIdx.x;
    int e = blockIdx.x * 32 + (t >> 3);
    int j = t & 7;
    float m = -3.402823e38f;
    if (e < E) {
        int src = ei[e], trg = ei[E + e], b = bids[e];
        const float4* ep = (const float4*)(edges + (size_t)e * EDGED_);
        float4 e0 = ep[j * 2], e1 = ep[j * 2 + 1];
        float ev[8] = {e0.x, e0.y, e0.z, e0.w, e1.x, e1.y, e1.z, e1.w};
        const float4* wb = (const float4*)(g_wae + b * (EDGED_ * H_) + j * 32);
        float4 acc = make_float4(0.f, 0.f, 0.f, 0.f);
        #pragma unroll
        for (int i = 0; i < 8; i++) {
            float4 w = wb[i];
            acc.x += ev[i] * w.x; acc.y += ev[i] * w.y;
            acc.z += ev[i] * w.z; acc.w += ev[i] * w.w;
        }
        #pragma unroll
        for (int mask = 1; mask <= 4; mask <<= 1) {
            acc.x += __shfl_xor_sync(~0u, acc.x, mask);
            acc.y += __shfl_xor_sync(~0u, acc.y, mask);
            acc.z += __shfl_xor_sync(~0u, acc.z, mask);
            acc.w += __shfl_xor_sync(~0u, acc.w, mask);
        }
        if (j == 0) {
            float4 sv = *(const float4*)(g_ss + src * H_);
            float4 tv = *(const float4*)(g_st + trg * H_);
            float4 s = make_float4(acc.x + sv.x + tv.x, acc.y + sv.y + tv.y,
                                   acc.z + sv.z + tv.z, acc.w + sv.w + tv.w);
            s.x = s.x > 0.f ? s.x : 0.2f * s.x;
            s.y = s.y > 0.f ? s.y : 0.2f * s.y;
            s.z = s.z > 0.f ? s.z : 0.2f * s.z;
            s.w = s.w > 0.f ? s.w : 0.2f * s.w;
            *((float4*)g_scores + e) = s;
            m = fmaxf(fmaxf(s.x, s.y), fmaxf(s.z, s.w));
        }
    }
    // block max reduction, one atomic per block
    __shared__ float wm[8];
    #pragma unroll
    for (int mask = 16; mask >= 1; mask >>= 1) m = fmaxf(m, __shfl_xor_sync(~0u, m, mask));
    if ((t & 31) == 0) wm[t >> 5] = m;
    __syncthreads();
    if (t < 8) {
        float v = wm[t];
        v = fmaxf(v, __shfl_xor_sync(0xffu, v, 4));
        v = fmaxf(v, __shfl_xor_sync(0xffu, v, 2));
        v = fmaxf(v, __shfl_xor_sync(0xffu, v, 1));
        if (t == 0) atomicMax(&g_gmax, encf(v));
    }
}

// ---------------- K3a: exp(score - max), denominators via float4 RED -------
__global__ void k3a_exp_denom(const int* __restrict__ ei, int E) {
    int e = blockIdx.x * blockDim.x + threadIdx.x;
    if (e >= E) return;
    float gm = decf(g_gmax);
    float4 s = *((float4*)g_scores + e);
    float4 ex = make_float4(expf(s.x - gm), expf(s.y - gm), expf(s.z - gm), expf(s.w - gm));
    *((float4*)g_scores + e) = ex;
    int src = ei[e], trg = ei[E + e];
    atomicAdd((float4*)(g_den_trg + trg * H_), ex);
    atomicAdd((float4*)(g_den_src + src * H_), ex);
}

// ---------------- K3inv: invert denominators once ---------------------------
__global__ void k3inv(int N) {
    int i = blockIdx.x * blockDim.x + threadIdx.x;
    if (i >= N * H_) return;
    g_den_src[i] = 1.f / (g_den_src[i] + 1e-16f);
    g_den_trg[i] = 1.f / (g_den_trg[i] + 1e-16f);
}

// ---------------- K3b: weighted scatter (warp per edge, float4 RED) --------
__global__ __launch_bounds__(256) void k3b_scatter(const int* __restrict__ ei, int E) {
    int e = (int)((blockIdx.x * 256 + threadIdx.x) >> 5);
    int lane = threadIdx.x & 31;
    if (e >= E) return;
    int src = ei[e], trg = ei[E + e];
    int h = lane >> 3;
    float ex = g_scores[e * H_ + h];
    float at = ex * g_den_trg[trg * H_ + h];   // attention toward trg branch
    float as = ex * g_den_src[src * H_ + h];   // attention toward src branch
    float4 ps = *((const float4*)g_proj + (size_t)src * 32 + lane);
    float4 pt = *((const float4*)g_proj + (size_t)trg * 32 + lane);
    float4 vt = make_float4(ps.x * at, ps.y * at, ps.z * at, ps.w * at);
    float4 vs = make_float4(pt.x * as, pt.y * as, pt.z * as, pt.w * as);
    atomicAdd((float4*)g_acc_trg + (size_t)trg * 32 + lane, vt);
    atomicAdd((float4*)g_acc_src + (size_t)src * 32 + lane, vs);
}

// ---------------- K4: concat + LayerNorm (warp per node) -------------------
__global__ __launch_bounds__(256) void k4_layernorm(
    const float* __restrict__ gamma, const float* __restrict__ beta,
    float* __restrict__ out, int N)
{
    int n = (int)((blockIdx.x * 256 + threadIdx.x) >> 5);
    int lane = threadIdx.x & 31;
    if (n >= N) return;
    float4 a = *((const float4*)g_acc_src + (size_t)n * 32 + lane);
    float4 b = *((const float4*)g_acc_trg + (size_t)n * 32 + lane);
    float s = a.x + a.y + a.z + a.w + b.x + b.y + b.z + b.w;
    float q = a.x * a.x + a.y * a.y + a.z * a.z + a.w * a.w +
              b.x * b.x + b.y * b.y + b.z * b.z + b.w * b.w;
    #pragma unroll
    for (int mask = 16; mask >= 1; mask >>= 1) {
        s += __shfl_xor_sync(~0u, s, mask);
        q += __shfl_xor_sync(~0u, q, mask);
    }
    float mu = s * (1.f / 256.f);
    float var = q * (1.f / 256.f) - mu * mu;
    float r = rsqrtf(var + 1e-5f);
    float4 g1 = ((const float4*)gamma)[lane];
    float4 be1 = ((const float4*)beta)[lane];
    float4 g2 = ((const float4*)gamma)[32 + lane];
    float4 be2 = ((const float4*)beta)[32 + lane];
    float4 o1 = make_float4((a.x - mu) * r * g1.x + be1.x, (a.y - mu) * r * g1.y + be1.y,
                            (a.z - mu) * r * g1.z + be1.z, (a.w - mu) * r * g1.w + be1.w);
    float4 o2 = make_float4((b.x - mu) * r * g2.x + be2.x, (b.y - mu) * r * g2.y + be2.y,
                            (b.z - mu) * r * g2.z + be2.z, (b.w - mu) * r * g2.w + be2.w);
    ((float4*)out)[(size_t)n * 64 + lane] = o1;
    ((float4*)out)[(size_t)n * 64 + 32 + lane] = o2;
}

// ---------------------------------------------------------------------------
static inline int cdiv(int a, int b) { return (a + b - 1) / b; }

extern "C" void kernel_launch(void* const* d_in, const int* in_sizes, int n_in,
                              void* d_out, int out_size)
{
    const float* x      = (const float*)d_in[0];
    const int*   ei     = (const int*)d_in[1];
    const float* edges  = (const float*)d_in[2];
    const float* ins    = (const float*)d_in[3];
    const int*   bids   = (const int*)d_in[4];
    // d_in[5] = max_local_entity (derived as N/B below, no device read needed)
    const float* Wp     = (const float*)d_in[6];
    const float* We     = (const float*)d_in[7];
    const float* Wsi    = (const float*)d_in[8];
    const float* bsi    = (const float*)d_in[9];
    const float* Wti    = (const float*)d_in[10];
    const float* bti    = (const float*)d_in[11];
    const float* Wei    = (const float*)d_in[12];
    const float* bei    = (const float*)d_in[13];
    const float* a_src  = (const float*)d_in[14];
    const float* a_trg  = (const float*)d_in[15];
    const float* a_edge = (const float*)d_in[16];
    const float* bias   = (const float*)d_in[17];
    const float* Wsk    = (const float*)d_in[18];
    const float* gamma  = (const float*)d_in[19];
    const float* beta   = (const float*)d_in[20];

    int N = in_sizes[0] / FIN_;
    int E = in_sizes[2] / EDGED_;
    int B = in_sizes[3] / HID_;
    int mle = N / B;

    k_init<<<cdiv(N * H_, 256), 256>>>(N);
    k0_batch<<<B, 128>>>(ins, Wsi, bsi, Wti, bti, Wei, bei, a_src, a_trg, a_edge, We);
    {
        dim3 grid(cdiv(N, 128), 2);
        k1_gemm<<<grid, 256>>>(x, Wp, Wsk, bias, N, mle);
    }
    k2_edge_scores<<<cdiv(E, 32), 256>>>(ei, edges, bids, E);
    k3a_exp_denom<<<cdiv(E, 256), 256>>>(ei, E);
    k3inv<<<cdiv(N * H_, 256), 256>>>(N);
    k3b_scatter<<<cdiv(E * 32, 256), 256>>>(ei, E);
    k4_layernorm<<<cdiv(N * 32, 256), 256>>>(gamma, beta, (float*)d_out, N);
}

// round 3
// speedup vs baseline: 1.1488x; 1.1054x over previous
#include <cuda_runtime.h>

#define H_     4
#define F_     32
#define HF_    128
#define FIN_   128
#define EDGED_ 64
#define HID_   256
#define BMAX_  64
#define NMAX_  96000
#define EMAX_  600000

// ---------------- scratch (device globals; no allocation allowed) ----------
__device__ float    g_proj[NMAX_ * HF_];
__device__ float    g_acc_src[NMAX_ * HF_];
__device__ float    g_acc_trg[NMAX_ * HF_];
__device__ float    g_ss[NMAX_ * H_];
__device__ float    g_st[NMAX_ * H_];
__device__ float    g_scores[EMAX_ * H_];       // scores, later overwritten with exp()
__device__ float    g_den_src[NMAX_ * H_];
__device__ float    g_den_trg[NMAX_ * H_];
__device__ float    g_asb[BMAX_ * HF_];         // a_src * src_bridge per batch
__device__ float    g_atb[BMAX_ * HF_];         // a_trg * trg_bridge per batch
__device__ float    g_waet[H_ * EDGED_ * BMAX_]; // folded edge matrix, [h][d][b]
__device__ unsigned g_gmax;                     // order-preserving encoded float max

#define WAE_PAD 65                               // smem row pad (bank = (d+b)%32)

// ordered-uint encoding of float (monotone)
__device__ __forceinline__ unsigned encf(float f) {
    unsigned u = __float_as_uint(f);
    return (u & 0x80000000u) ? ~u : (u | 0x80000000u);
}
__device__ __forceinline__ float decf(unsigned u) {
    return (u & 0x80000000u) ? __uint_as_float(u ^ 0x80000000u) : __uint_as_float(~u);
}

// ---- packed f32x2 helpers (sm_103a FFMA2 path, PTX-only) -------------------
__device__ __forceinline__ unsigned long long packdup(float x) {
    unsigned long long r;
    asm("mov.b64 %0, {%1, %1};" : "=l"(r) : "f"(x));
    return r;
}
__device__ __forceinline__ float2 unpk(unsigned long long v) {
    float2 r;
    asm("mov.b64 {%0, %1}, %2;" : "=f"(r.x), "=f"(r.y) : "l"(v));
    return r;
}
__device__ __forceinline__ void fma2(unsigned long long& acc, unsigned long long a,
                                     unsigned long long b) {
    asm("fma.rn.f32x2 %0, %1, %2, %0;" : "+l"(acc) : "l"(a), "l"(b));
}
__device__ __forceinline__ unsigned long long add2(unsigned long long a,
                                                   unsigned long long b) {
    unsigned long long r;
    asm("add.rn.f32x2 %0, %1, %2;" : "=l"(r) : "l"(a), "l"(b));
    return r;
}

// ---------------- K_init: zero denominators, reset global max --------------
__global__ void k_init(int N) {
    int i = blockIdx.x * blockDim.x + threadIdx.x;
    if (i == 0) g_gmax = 0u;   // 0 < encf(any float)
    if (i < N * H_) { g_den_src[i] = 0.f; g_den_trg[i] = 0.f; }
}

// ---------------- K0: per-batch instruction bridges + folded edge matrix ---
__global__ __launch_bounds__(128) void k0_batch(
    const float* __restrict__ ins,
    const float* __restrict__ Wsi, const float* __restrict__ bsi,
    const float* __restrict__ Wti, const float* __restrict__ bti,
    const float* __restrict__ Wei, const float* __restrict__ bei,
    const float* __restrict__ a_src, const float* __restrict__ a_trg,
    const float* __restrict__ a_edge, const float* __restrict__ W_edge)
{
    __shared__ float si[HID_];
    __shared__ float aeb[HF_];
    int b = blockIdx.x, t = threadIdx.x;
    si[t] = ins[b * HID_ + t];
    si[t + 128] = ins[b * HID_ + t + 128];
    __syncthreads();

    float s1 = bsi[t], s2 = bti[t], s3 = bei[t];
    #pragma unroll 4
    for (int k = 0; k < HID_; k++) {
        float iv = si[k];
        s1 += iv * Wsi[k * HF_ + t];
        s2 += iv * Wti[k * HF_ + t];
        s3 += iv * Wei[k * HF_ + t];
    }
    g_asb[b * HF_ + t] = a_src[t] * s1;
    g_atb[b * HF_ + t] = a_trg[t] * s2;
    aeb[t] = a_edge[t] * s3;
    __syncthreads();

    // waet[h][d][b] = sum_f W_edge[d, h*32+f] * aeb[h*32+f]
    #pragma unroll
    for (int r = 0; r < 2; r++) {
        int idx = t + r * 128;
        int d = idx >> 2, h = idx & 3;
        float w = 0.f;
        #pragma unroll
        for (int f = 0; f < F_; f++) w += W_edge[d * HF_ + h * F_ + f] * aeb[h * F_ + f];
        g_waet[(h * EDGED_ + d) * BMAX_ + b] = w;
    }
}

// ---------------- K1: fused GEMM  x @ [W_proj | W_skip], FFMA2 mainloop ----
// 128x128 tile per block, BK=8, 256 threads, 8x8 microtile as 8x(4 f32x2).
// blockIdx.y==0 -> proj + fused node scores; ==1 -> skip(+bias) to both accs.
__global__ __launch_bounds__(256) void k1_gemm(
    const float* __restrict__ x, const float* __restrict__ Wp,
    const float* __restrict__ Wsk, const float* __restrict__ bias,
    int N, int mle)
{
    __shared__ float As[8][128];
    __shared__ float Bs[8][128];
    const float* W = (blockIdx.y == 0) ? Wp : Wsk;
    int t = threadIdx.x;
    int row0 = blockIdx.x * 128;
    int tx = t & 15, ty = t >> 4;

    unsigned long long acc2[8][4];
    #pragma unroll
    for (int i = 0; i < 8; i++)
        #pragma unroll
        for (int j = 0; j < 4; j++) acc2[i][j] = 0ull;

    int lr = t >> 1, lq = t & 1;          // A tile: row lr, float4 quad lq
    int bk = t >> 5, bc = (t & 31) * 4;   // B tile

    for (int k0 = 0; k0 < FIN_; k0 += 8) {
        int arow = row0 + lr;
        float4 av = make_float4(0.f, 0.f, 0.f, 0.f);
        if (arow < N) av = *(const float4*)(x + (size_t)arow * FIN_ + k0 + lq * 4);
        As[lq * 4 + 0][lr] = av.x; As[lq * 4 + 1][lr] = av.y;
        As[lq * 4 + 2][lr] = av.z; As[lq * 4 + 3][lr] = av.w;
        float4 bv = *(const float4*)(W + (size_t)(k0 + bk) * HF_ + bc);
        *(float4*)(&Bs[bk][bc]) = bv;
        __syncthreads();

        #pragma unroll
        for (int kk = 0; kk < 8; kk++) {
            float4 a0 = *(float4*)(&As[kk][ty * 8]);
            float4 a1 = *(float4*)(&As[kk][ty * 8 + 4]);
            ulonglong2 bp0 = *(const ulonglong2*)(&Bs[kk][tx * 8]);
            ulonglong2 bp1 = *(const ulonglong2*)(&Bs[kk][tx * 8 + 4]);
            unsigned long long bb[4] = {bp0.x, bp0.y, bp1.x, bp1.y};
            float a[8] = {a0.x, a0.y, a0.z, a0.w, a1.x, a1.y, a1.z, a1.w};
            #pragma unroll
            for (int i = 0; i < 8; i++) {
                unsigned long long aa = packdup(a[i]);
                fma2(acc2[i][0], aa, bb[0]);
                fma2(acc2[i][1], aa, bb[1]);
                fma2(acc2[i][2], aa, bb[2]);
                fma2(acc2[i][3], aa, bb[3]);
            }
        }
        __syncthreads();
    }

    if (blockIdx.y == 0) {
        // proj store + fused node-score partials.
        int head = tx >> 2;
        #pragma unroll
        for (int i = 0; i < 8; i++) {
            int row = row0 + ty * 8 + i;
            int rc = row < N ? row : N - 1;
            int b = rc / mle;
            float2 c0 = unpk(acc2[i][0]);
            float2 c1 = unpk(acc2[i][1]);
            float2 c2 = unpk(acc2[i][2]);
            float2 c3 = unpk(acc2[i][3]);
            if (row < N) {
                float4 v0 = make_float4(c0.x, c0.y, c1.x, c1.y);
                float4 v1 = make_float4(c2.x, c2.y, c3.x, c3.y);
                *(float4*)(g_proj + (size_t)row * HF_ + tx * 8) = v0;
                *(float4*)(g_proj + (size_t)row * HF_ + tx * 8 + 4) = v1;
            }
            const float4* ab = (const float4*)(g_asb + b * HF_ + tx * 8);
            const float4* tb = (const float4*)(g_atb + b * HF_ + tx * 8);
            float4 ab0 = ab[0], ab1 = ab[1];
            float4 tb0 = tb[0], tb1 = tb[1];
            float s = c0.x * ab0.x + c0.y * ab0.y + c1.x * ab0.z + c1.y * ab0.w
                    + c2.x * ab1.x + c2.y * ab1.y + c3.x * ab1.z + c3.y * ab1.w;
            float u = c0.x * tb0.x + c0.y * tb0.y + c1.x * tb0.z + c1.y * tb0.w
                    + c2.x * tb1.x + c2.y * tb1.y + c3.x * tb1.z + c3.y * tb1.w;
            s += __shfl_xor_sync(~0u, s, 1);
            s += __shfl_xor_sync(~0u, s, 2);
            u += __shfl_xor_sync(~0u, u, 1);
            u += __shfl_xor_sync(~0u, u, 2);
            if ((tx & 3) == 0 && row < N) {
                g_ss[row * H_ + head] = s;
                g_st[row * H_ + head] = u;
            }
        }
    } else {
        const ulonglong2* bp = (const ulonglong2*)(bias + tx * 8);
        ulonglong2 bq0 = bp[0], bq1 = bp[1];
        unsigned long long bpk[4] = {bq0.x, bq0.y, bq1.x, bq1.y};
        #pragma unroll
        for (int i = 0; i < 8; i++) {
            int row = row0 + ty * 8 + i;
            if (row >= N) break;
            ulonglong2 w0, w1;
            w0.x = add2(acc2[i][0], bpk[0]);
            w0.y = add2(acc2[i][1], bpk[1]);
            w1.x = add2(acc2[i][2], bpk[2]);
            w1.y = add2(acc2[i][3], bpk[3]);
            *(ulonglong2*)(g_acc_src + (size_t)row * HF_ + tx * 8) = w0;
            *(ulonglong2*)(g_acc_src + (size_t)row * HF_ + tx * 8 + 4) = w1;
            *(ulonglong2*)(g_acc_trg + (size_t)row * HF_ + tx * 8) = w0;
            *(ulonglong2*)(g_acc_trg + (size_t)row * HF_ + tx * 8 + 4) = w1;
        }
    }
}

// ---------------- K2: per-edge scores, folded matrix in SMEM ----------------
// Grid-stride over 4-edge groups, 8 lanes per edge, thread j handles
// d = 8*dd + j (dd = 0..7). Folded matrix cached in smem as [h][d][b] with
// row pad 65 so bank = (d + b) % 32 (edge's 8 lanes -> 8 consecutive banks).
__global__ __launch_bounds__(256) void k2_edge_scores(
    const int* __restrict__ ei, const float* __restrict__ edges,
    const int* __restrict__ bids, int E)
{
    extern __shared__ float s_w[];   // [H_*EDGED_][WAE_PAD] = 4*64*65 floats
    int t = threadIdx.x;

    // cooperative preload of the 64 KB folded table (pad-inserted)
    #pragma unroll
    for (int i = t; i < H_ * EDGED_ * BMAX_; i += 256) {
        int hd = i >> 6, b = i & 63;
        s_w[hd * WAE_PAD + b] = g_waet[i];
    }
    __syncthreads();

    int lane = t & 31;
    int j = lane & 7;             // lane within edge
    int esub = lane >> 3;         // edge within group (0..3)
    int gw = (blockIdx.x * 256 + t) >> 5;       // global warp
    int nwarps = gridDim.x * 8;
    int G = (E + 3) >> 2;                        // 4-edge groups

    float m = -3.402823e38f;

    for (int g = gw; g < G; g += nwarps) {
        int e = g * 4 + esub;
        bool eok = e < E;
        int ec = eok ? e : E - 1;
        int b = bids[ec];

        // edge features: thread j covers d = j, j+8, ..., j+56 (sector-packed)
        float ev[8];
        const float* erow = edges + (size_t)ec * EDGED_ + j;
        #pragma unroll
        for (int dd = 0; dd < 8; dd++) ev[dd] = erow[dd * 8];

        const float* wp = s_w + j * WAE_PAD + b;
        float a0 = 0.f, a1 = 0.f, a2 = 0.f, a3 = 0.f;
        #pragma unroll
        for (int dd = 0; dd < 8; dd++) {
            float evv = ev[dd];
            const float* wq = wp + dd * (8 * WAE_PAD);
            a0 += evv * wq[0];
            a1 += evv * wq[64 * WAE_PAD];
            a2 += evv * wq[128 * WAE_PAD];
            a3 += evv * wq[192 * WAE_PAD];
        }
        #pragma unroll
        for (int mask = 1; mask <= 4; mask <<= 1) {
            a0 += __shfl_xor_sync(~0u, a0, mask);
            a1 += __shfl_xor_sync(~0u, a1, mask);
            a2 += __shfl_xor_sync(~0u, a2, mask);
            a3 += __shfl_xor_sync(~0u, a3, mask);
        }
        if (j == 0 && eok) {
            int src = ei[e], trg = ei[E + e];
            float4 sv = *(const float4*)(g_ss + src * H_);
            float4 tv = *(const float4*)(g_st + trg * H_);
            float4 s = make_float4(a0 + sv.x + tv.x, a1 + sv.y + tv.y,
                                   a2 + sv.z + tv.z, a3 + sv.w + tv.w);
            s.x = s.x > 0.f ? s.x : 0.2f * s.x;
            s.y = s.y > 0.f ? s.y : 0.2f * s.y;
            s.z = s.z > 0.f ? s.z : 0.2f * s.z;
            s.w = s.w > 0.f ? s.w : 0.2f * s.w;
            *((float4*)g_scores + e) = s;
            m = fmaxf(m, fmaxf(fmaxf(s.x, s.y), fmaxf(s.z, s.w)));
        }
    }

    // block max reduction, one atomic per block
    __shared__ float wm[8];
    #pragma unroll
    for (int mask = 16; mask >= 1; mask >>= 1) m = fmaxf(m, __shfl_xor_sync(~0u, m, mask));
    if ((t & 31) == 0) wm[t >> 5] = m;
    __syncthreads();
    if (t < 8) {
        float v = wm[t];
        v = fmaxf(v, __shfl_xor_sync(0xffu, v, 4));
        v = fmaxf(v, __shfl_xor_sync(0xffu, v, 2));
        v = fmaxf(v, __shfl_xor_sync(0xffu, v, 1));
        if (t == 0) atomicMax(&g_gmax, encf(v));
    }
}

// ---------------- K3a: exp(score - max), denominators via float4 RED -------
__global__ void k3a_exp_denom(const int* __restrict__ ei, int E) {
    int e = blockIdx.x * blockDim.x + threadIdx.x;
    if (e >= E) return;
    float gm = decf(g_gmax);
    float4 s = *((float4*)g_scores + e);
    float4 ex = make_float4(expf(s.x - gm), expf(s.y - gm), expf(s.z - gm), expf(s.w - gm));
    *((float4*)g_scores + e) = ex;
    int src = ei[e], trg = ei[E + e];
    atomicAdd((float4*)(g_den_trg + trg * H_), ex);
    atomicAdd((float4*)(g_den_src + src * H_), ex);
}

// ---------------- K3inv: invert denominators once ---------------------------
__global__ void k3inv(int N) {
    int i = blockIdx.x * blockDim.x + threadIdx.x;
    if (i >= N * H_) return;
    g_den_src[i] = 1.f / (g_den_src[i] + 1e-16f);
    g_den_trg[i] = 1.f / (g_den_trg[i] + 1e-16f);
}

// ---------------- K3b: weighted scatter (warp per edge, float4 RED) --------
__global__ __launch_bounds__(256) void k3b_scatter(const int* __restrict__ ei, int E) {
    int e = (int)((blockIdx.x * 256 + threadIdx.x) >> 5);
    int lane = threadIdx.x & 31;
    if (e >= E) return;
    int src = ei[e], trg = ei[E + e];
    int h = lane >> 3;
    float ex = g_scores[e * H_ + h];
    float at = ex * g_den_trg[trg * H_ + h];   // attention toward trg branch
    float as = ex * g_den_src[src * H_ + h];   // attention toward src branch
    float4 ps = *((const float4*)g_proj + (size_t)src * 32 + lane);
    float4 pt = *((const float4*)g_proj + (size_t)trg * 32 + lane);
    float4 vt = make_float4(ps.x * at, ps.y * at, ps.z * at, ps.w * at);
    float4 vs = make_float4(pt.x * as, pt.y * as, pt.z * as, pt.w * as);
    atomicAdd((float4*)g_acc_trg + (size_t)trg * 32 + lane, vt);
    atomicAdd((float4*)g_acc_src + (size_t)src * 32 + lane, vs);
}

// ---------------- K4: concat + LayerNorm (warp per node) -------------------
__global__ __launch_bounds__(256) void k4_layernorm(
    const float* __restrict__ gamma, const float* __restrict__ beta,
    float* __restrict__ out, int N)
{
    int n = (int)((blockIdx.x * 256 + threadIdx.x) >> 5);
    int lane = threadIdx.x & 31;
    if (n >= N) return;
    float4 a = *((const float4*)g_acc_src + (size_t)n * 32 + lane);
    float4 b = *((const float4*)g_acc_trg + (size_t)n * 32 + lane);
    float s = a.x + a.y + a.z + a.w + b.x + b.y + b.z + b.w;
    float q = a.x * a.x + a.y * a.y + a.z * a.z + a.w * a.w +
              b.x * b.x + b.y * b.y + b.z * b.z + b.w * b.w;
    #pragma unroll
    for (int mask = 16; mask >= 1; mask >>= 1) {
        s += __shfl_xor_sync(~0u, s, mask);
        q += __shfl_xor_sync(~0u, q, mask);
    }
    float mu = s * (1.f / 256.f);
    float var = q * (1.f / 256.f) - mu * mu;
    float r = rsqrtf(var + 1e-5f);
    float4 g1 = ((const float4*)gamma)[lane];
    float4 be1 = ((const float4*)beta)[lane];
    float4 g2 = ((const float4*)gamma)[32 + lane];
    float4 be2 = ((const float4*)beta)[32 + lane];
    float4 o1 = make_float4((a.x - mu) * r * g1.x + be1.x, (a.y - mu) * r * g1.y + be1.y,
                            (a.z - mu) * r * g1.z + be1.z, (a.w - mu) * r * g1.w + be1.w);
    float4 o2 = make_float4((b.x - mu) * r * g2.x + be2.x, (b.y - mu) * r * g2.y + be2.y,
                            (b.z - mu) * r * g2.z + be2.z, (b.w - mu) * r * g2.w + be2.w);
    ((float4*)out)[(size_t)n * 64 + lane] = o1;
    ((float4*)out)[(size_t)n * 64 + 32 + lane] = o2;
}

// ---------------------------------------------------------------------------
static inline int cdiv(int a, int b) { return (a + b - 1) / b; }

extern "C" void kernel_launch(void* const* d_in, const int* in_sizes, int n_in,
                              void* d_out, int out_size)
{
    const float* x      = (const float*)d_in[0];
    const int*   ei     = (const int*)d_in[1];
    const float* edges  = (const float*)d_in[2];
    const float* ins    = (const float*)d_in[3];
    const int*   bids   = (const int*)d_in[4];
    // d_in[5] = max_local_entity (derived as N/B below, no device read needed)
    const float* Wp     = (const float*)d_in[6];
    const float* We     = (const float*)d_in[7];
    const float* Wsi    = (const float*)d_in[8];
    const float* bsi    = (const float*)d_in[9];
    const float* Wti    = (const float*)d_in[10];
    const float* bti    = (const float*)d_in[11];
    const float* Wei    = (const float*)d_in[12];
    const float* bei    = (const float*)d_in[13];
    const float* a_src  = (const float*)d_in[14];
    const float* a_trg  = (const float*)d_in[15];
    const float* a_edge = (const float*)d_in[16];
    const float* bias   = (const float*)d_in[17];
    const float* Wsk    = (const float*)d_in[18];
    const float* gamma  = (const float*)d_in[19];
    const float* beta   = (const float*)d_in[20];

    int N = in_sizes[0] / FIN_;
    int E = in_sizes[2] / EDGED_;
    int B = in_sizes[3] / HID_;
    int mle = N / B;

    const int k2_smem = H_ * EDGED_ * WAE_PAD * (int)sizeof(float);  // 66560 B
    cudaFuncSetAttribute(k2_edge_scores,
                         cudaFuncAttributeMaxDynamicSharedMemorySize, k2_smem);

    k_init<<<cdiv(N * H_, 256), 256>>>(N);
    k0_batch<<<B, 128>>>(ins, Wsi, bsi, Wti, bti, Wei, bei, a_src, a_trg, a_edge, We);
    {
        dim3 grid(cdiv(N, 128), 2);
        k1_gemm<<<grid, 256>>>(x, Wp, Wsk, bias, N, mle);
    }
    k2_edge_scores<<<444, 256, k2_smem>>>(ei, edges, bids, E);
    k3a_exp_denom<<<cdiv(E, 256), 256>>>(ei, E);
    k3inv<<<cdiv(N * H_, 256), 256>>>(N);
    k3b_scatter<<<cdiv(E * 32, 256), 256>>>(ei, E);
    k4_layernorm<<<cdiv(N * 32, 256), 256>>>(gamma, beta, (float*)d_out, N);
}

// round 4
// speedup vs baseline: 1.1881x; 1.0342x over previous
#include <cuda_runtime.h>

#define H_     4
#define F_     32
#define HF_    128
#define FIN_   128
#define EDGED_ 64
#define HID_   256
#define BMAX_  64
#define NMAX_  96000
#define EMAX_  600000

// ---------------- scratch (device globals; no allocation allowed) ----------
__device__ float    g_proj[NMAX_ * HF_];
__device__ float    g_acc_src[NMAX_ * HF_];
__device__ float    g_acc_trg[NMAX_ * HF_];
__device__ float    g_ss[NMAX_ * H_];
__device__ float    g_st[NMAX_ * H_];
__device__ float    g_scores[EMAX_ * H_];       // scores, later overwritten with exp()
__device__ float    g_den_src[NMAX_ * H_];
__device__ float    g_den_trg[NMAX_ * H_];
__device__ float    g_asb[BMAX_ * HF_];         // a_src * src_bridge per batch
__device__ float    g_atb[BMAX_ * HF_];         // a_trg * trg_bridge per batch
__device__ float    g_waet[H_ * EDGED_ * BMAX_]; // folded edge matrix, [h][dperm][b]
__device__ unsigned g_gmax;                     // order-preserving encoded float max

#define WAE_PAD 65                               // smem row pad (bank = (d+b)%32)

// ordered-uint encoding of float (monotone)
__device__ __forceinline__ unsigned encf(float f) {
    unsigned u = __float_as_uint(f);
    return (u & 0x80000000u) ? ~u : (u | 0x80000000u);
}
__device__ __forceinline__ float decf(unsigned u) {
    return (u & 0x80000000u) ? __uint_as_float(u ^ 0x80000000u) : __uint_as_float(~u);
}

// ---- packed f32x2 helpers (sm_103a FFMA2 path, PTX-only) -------------------
__device__ __forceinline__ unsigned long long packdup(float x) {
    unsigned long long r;
    asm("mov.b64 %0, {%1, %1};" : "=l"(r) : "f"(x));
    return r;
}
__device__ __forceinline__ float2 unpk(unsigned long long v) {
    float2 r;
    asm("mov.b64 {%0, %1}, %2;" : "=f"(r.x), "=f"(r.y) : "l"(v));
    return r;
}
__device__ __forceinline__ void fma2(unsigned long long& acc, unsigned long long a,
                                     unsigned long long b) {
    asm("fma.rn.f32x2 %0, %1, %2, %0;" : "+l"(acc) : "l"(a), "l"(b));
}
__device__ __forceinline__ unsigned long long add2(unsigned long long a,
                                                   unsigned long long b) {
    unsigned long long r;
    asm("add.rn.f32x2 %0, %1, %2;" : "=l"(r) : "l"(a), "l"(b));
    return r;
}

// ---------------- K_init: zero denominators, reset global max --------------
__global__ void k_init(int N) {
    int i = blockIdx.x * blockDim.x + threadIdx.x;
    if (i == 0) g_gmax = 0u;   // 0 < encf(any float)
    if (i < N * H_) { g_den_src[i] = 0.f; g_den_trg[i] = 0.f; }
}

// ---------------- K0: per-batch instruction bridges + folded edge matrix ---
__global__ __launch_bounds__(128) void k0_batch(
    const float* __restrict__ ins,
    const float* __restrict__ Wsi, const float* __restrict__ bsi,
    const float* __restrict__ Wti, const float* __restrict__ bti,
    const float* __restrict__ Wei, const float* __restrict__ bei,
    const float* __restrict__ a_src, const float* __restrict__ a_trg,
    const float* __restrict__ a_edge, const float* __restrict__ W_edge)
{
    __shared__ float si[HID_];
    __shared__ float aeb[HF_];
    int b = blockIdx.x, t = threadIdx.x;
    si[t] = ins[b * HID_ + t];
    si[t + 128] = ins[b * HID_ + t + 128];
    __syncthreads();

    float s1 = bsi[t], s2 = bti[t], s3 = bei[t];
    #pragma unroll 4
    for (int k = 0; k < HID_; k++) {
        float iv = si[k];
        s1 += iv * Wsi[k * HF_ + t];
        s2 += iv * Wti[k * HF_ + t];
        s3 += iv * Wei[k * HF_ + t];
    }
    g_asb[b * HF_ + t] = a_src[t] * s1;
    g_atb[b * HF_ + t] = a_trg[t] * s2;
    aeb[t] = a_edge[t] * s3;
    __syncthreads();

    // waet[h][p][b], p = ((d&7)<<3)|(d>>3)  (k2 thread j owns d = 8j..8j+7)
    #pragma unroll
    for (int r = 0; r < 2; r++) {
        int idx = t + r * 128;
        int d = idx >> 2, h = idx & 3;
        float w = 0.f;
        #pragma unroll
        for (int f = 0; f < F_; f++) w += W_edge[d * HF_ + h * F_ + f] * aeb[h * F_ + f];
        int p = ((d & 7) << 3) | (d >> 3);
        g_waet[(h * EDGED_ + p) * BMAX_ + b] = w;
    }
}

// ---------------- K1: fused GEMM  x @ [W_proj | W_skip], FFMA2 mainloop ----
__global__ __launch_bounds__(256) void k1_gemm(
    const float* __restrict__ x, const float* __restrict__ Wp,
    const float* __restrict__ Wsk, const float* __restrict__ bias,
    int N, int mle)
{
    __shared__ float As[8][128];
    __shared__ float Bs[8][128];
    const float* W = (blockIdx.y == 0) ? Wp : Wsk;
    int t = threadIdx.x;
    int row0 = blockIdx.x * 128;
    int tx = t & 15, ty = t >> 4;

    unsigned long long acc2[8][4];
    #pragma unroll
    for (int i = 0; i < 8; i++)
        #pragma unroll
        for (int j = 0; j < 4; j++) acc2[i][j] = 0ull;

    int lr = t >> 1, lq = t & 1;          // A tile: row lr, float4 quad lq
    int bk = t >> 5, bc = (t & 31) * 4;   // B tile

    for (int k0 = 0; k0 < FIN_; k0 += 8) {
        int arow = row0 + lr;
        float4 av = make_float4(0.f, 0.f, 0.f, 0.f);
        if (arow < N) av = *(const float4*)(x + (size_t)arow * FIN_ + k0 + lq * 4);
        As[lq * 4 + 0][lr] = av.x; As[lq * 4 + 1][lr] = av.y;
        As[lq * 4 + 2][lr] = av.z; As[lq * 4 + 3][lr] = av.w;
        float4 bv = *(const float4*)(W + (size_t)(k0 + bk) * HF_ + bc);
        *(float4*)(&Bs[bk][bc]) = bv;
        __syncthreads();

        #pragma unroll
        for (int kk = 0; kk < 8; kk++) {
            float4 a0 = *(float4*)(&As[kk][ty * 8]);
            float4 a1 = *(float4*)(&As[kk][ty * 8 + 4]);
            ulonglong2 bp0 = *(const ulonglong2*)(&Bs[kk][tx * 8]);
            ulonglong2 bp1 = *(const ulonglong2*)(&Bs[kk][tx * 8 + 4]);
            unsigned long long bb[4] = {bp0.x, bp0.y, bp1.x, bp1.y};
            float a[8] = {a0.x, a0.y, a0.z, a0.w, a1.x, a1.y, a1.z, a1.w};
            #pragma unroll
            for (int i = 0; i < 8; i++) {
                unsigned long long aa = packdup(a[i]);
                fma2(acc2[i][0], aa, bb[0]);
                fma2(acc2[i][1], aa, bb[1]);
                fma2(acc2[i][2], aa, bb[2]);
                fma2(acc2[i][3], aa, bb[3]);
            }
        }
        __syncthreads();
    }

    if (blockIdx.y == 0) {
        int head = tx >> 2;
        #pragma unroll
        for (int i = 0; i < 8; i++) {
            int row = row0 + ty * 8 + i;
            int rc = row < N ? row : N - 1;
            int b = rc / mle;
            float2 c0 = unpk(acc2[i][0]);
            float2 c1 = unpk(acc2[i][1]);
            float2 c2 = unpk(acc2[i][2]);
            float2 c3 = unpk(acc2[i][3]);
            if (row < N) {
                float4 v0 = make_float4(c0.x, c0.y, c1.x, c1.y);
                float4 v1 = make_float4(c2.x, c2.y, c3.x, c3.y);
                *(float4*)(g_proj + (size_t)row * HF_ + tx * 8) = v0;
                *(float4*)(g_proj + (size_t)row * HF_ + tx * 8 + 4) = v1;
            }
            const float4* ab = (const float4*)(g_asb + b * HF_ + tx * 8);
            const float4* tb = (const float4*)(g_atb + b * HF_ + tx * 8);
            float4 ab0 = ab[0], ab1 = ab[1];
            float4 tb0 = tb[0], tb1 = tb[1];
            float s = c0.x * ab0.x + c0.y * ab0.y + c1.x * ab0.z + c1.y * ab0.w
                    + c2.x * ab1.x + c2.y * ab1.y + c3.x * ab1.z + c3.y * ab1.w;
            float u = c0.x * tb0.x + c0.y * tb0.y + c1.x * tb0.z + c1.y * tb0.w
                    + c2.x * tb1.x + c2.y * tb1.y + c3.x * tb1.z + c3.y * tb1.w;
            s += __shfl_xor_sync(~0u, s, 1);
            s += __shfl_xor_sync(~0u, s, 2);
            u += __shfl_xor_sync(~0u, u, 1);
            u += __shfl_xor_sync(~0u, u, 2);
            if ((tx & 3) == 0 && row < N) {
                g_ss[row * H_ + head] = s;
                g_st[row * H_ + head] = u;
            }
        }
    } else {
        const ulonglong2* bp = (const ulonglong2*)(bias + tx * 8);
        ulonglong2 bq0 = bp[0], bq1 = bp[1];
        unsigned long long bpk[4] = {bq0.x, bq0.y, bq1.x, bq1.y};
        #pragma unroll
        for (int i = 0; i < 8; i++) {
            int row = row0 + ty * 8 + i;
            if (row >= N) break;
            ulonglong2 w0, w1;
            w0.x = add2(acc2[i][0], bpk[0]);
            w0.y = add2(acc2[i][1], bpk[1]);
            w1.x = add2(acc2[i][2], bpk[2]);
            w1.y = add2(acc2[i][3], bpk[3]);
            *(ulonglong2*)(g_acc_src + (size_t)row * HF_ + tx * 8) = w0;
            *(ulonglong2*)(g_acc_src + (size_t)row * HF_ + tx * 8 + 4) = w1;
            *(ulonglong2*)(g_acc_trg + (size_t)row * HF_ + tx * 8) = w0;
            *(ulonglong2*)(g_acc_trg + (size_t)row * HF_ + tx * 8 + 4) = w1;
        }
    }
}

// ---------------- K2: per-edge scores, folded matrix in SMEM ----------------
// 1024-thread blocks (2/SM -> full occupancy with the 66.5KB table).
// 8 lanes per edge; thread j owns d = 8j..8j+7 (2x LDG.128, coalesced).
// Table permuted in k0 so smem index is (h*64 + dd*8 + j)*65 + b:
// bank = (j + b + const) % 32 -> 8 consecutive banks per edge.
__global__ __launch_bounds__(1024) void k2_edge_scores(
    const int* __restrict__ ei, const float* __restrict__ edges,
    const int* __restrict__ bids, int E)
{
    extern __shared__ float s_w[];   // [H_*EDGED_][WAE_PAD]
    int t = threadIdx.x;

    for (int i = t; i < H_ * EDGED_ * BMAX_; i += 1024) {
        int hd = i >> 6, b = i & 63;
        s_w[hd * WAE_PAD + b] = g_waet[i];
    }
    __syncthreads();

    int lane = t & 31;
    int j = lane & 7;             // lane within edge
    int esub = lane >> 3;         // edge within group (0..3)
    int gw = (blockIdx.x * 1024 + t) >> 5;      // global warp
    int nwarps = gridDim.x * 32;
    int G = (E + 3) >> 2;                        // 4-edge groups

    float m = -3.402823e38f;

    for (int g = gw; g < G; g += nwarps) {
        int e = g * 4 + esub;
        bool eok = e < E;
        int ec = eok ? e : E - 1;
        int b = bids[ec];

        // edge features: thread j covers d = 8j..8j+7 (contiguous, 2x float4)
        const float4* er = (const float4*)(edges + (size_t)ec * EDGED_ + j * 8);
        float4 q0 = er[0], q1 = er[1];
        float ev[8] = {q0.x, q0.y, q0.z, q0.w, q1.x, q1.y, q1.z, q1.w};

        const float* wp = s_w + j * WAE_PAD + b;
        float a0 = 0.f, a1 = 0.f, a2 = 0.f, a3 = 0.f;
        #pragma unroll
        for (int dd = 0; dd < 8; dd++) {
            float evv = ev[dd];
            const float* wq = wp + dd * (8 * WAE_PAD);
            a0 += evv * wq[0];
            a1 += evv * wq[64 * WAE_PAD];
            a2 += evv * wq[128 * WAE_PAD];
            a3 += evv * wq[192 * WAE_PAD];
        }
        #pragma unroll
        for (int mask = 1; mask <= 4; mask <<= 1) {
            a0 += __shfl_xor_sync(~0u, a0, mask);
            a1 += __shfl_xor_sync(~0u, a1, mask);
            a2 += __shfl_xor_sync(~0u, a2, mask);
            a3 += __shfl_xor_sync(~0u, a3, mask);
        }
        if (j == 0 && eok) {
            int src = ei[e], trg = ei[E + e];
            float4 sv = *(const float4*)(g_ss + src * H_);
            float4 tv = *(const float4*)(g_st + trg * H_);
            float4 s = make_float4(a0 + sv.x + tv.x, a1 + sv.y + tv.y,
                                   a2 + sv.z + tv.z, a3 + sv.w + tv.w);
            s.x = s.x > 0.f ? s.x : 0.2f * s.x;
            s.y = s.y > 0.f ? s.y : 0.2f * s.y;
            s.z = s.z > 0.f ? s.z : 0.2f * s.z;
            s.w = s.w > 0.f ? s.w : 0.2f * s.w;
            *((float4*)g_scores + e) = s;
            m = fmaxf(m, fmaxf(fmaxf(s.x, s.y), fmaxf(s.z, s.w)));
        }
    }

    // block max reduction, one atomic per block
    __shared__ float wm[32];
    #pragma unroll
    for (int mask = 16; mask >= 1; mask >>= 1) m = fmaxf(m, __shfl_xor_sync(~0u, m, mask));
    if ((t & 31) == 0) wm[t >> 5] = m;
    __syncthreads();
    if (t < 32) {
        float v = wm[t];
        #pragma unroll
        for (int mask = 16; mask >= 1; mask >>= 1) v = fmaxf(v, __shfl_xor_sync(~0u, v, mask));
        if (t == 0) atomicMax(&g_gmax, encf(v));
    }
}

// ---------------- K3a: exp(score - max), denominators via float4 RED -------
__global__ void k3a_exp_denom(const int* __restrict__ ei, int E) {
    int e = blockIdx.x * blockDim.x + threadIdx.x;
    if (e >= E) return;
    float gm = decf(g_gmax);
    float4 s = *((float4*)g_scores + e);
    float4 ex = make_float4(expf(s.x - gm), expf(s.y - gm), expf(s.z - gm), expf(s.w - gm));
    *((float4*)g_scores + e) = ex;
    int src = ei[e], trg = ei[E + e];
    atomicAdd((float4*)(g_den_trg + trg * H_), ex);
    atomicAdd((float4*)(g_den_src + src * H_), ex);
}

// ---------------- K3inv: invert denominators once ---------------------------
__global__ void k3inv(int N) {
    int i = blockIdx.x * blockDim.x + threadIdx.x;
    if (i >= N * H_) return;
    g_den_src[i] = 1.f / (g_den_src[i] + 1e-16f);
    g_den_trg[i] = 1.f / (g_den_trg[i] + 1e-16f);
}

// ---------------- K3b: weighted scatter (warp per edge, float4 RED) --------
__global__ __launch_bounds__(256) void k3b_scatter(const int* __restrict__ ei, int E) {
    int e = (int)((blockIdx.x * 256 + threadIdx.x) >> 5);
    int lane = threadIdx.x & 31;
    if (e >= E) return;
    int src = ei[e], trg = ei[E + e];
    int h = lane >> 3;
    float ex = g_scores[e * H_ + h];
    float at = ex * g_den_trg[trg * H_ + h];   // attention toward trg branch
    float as = ex * g_den_src[src * H_ + h];   // attention toward src branch
    float4 ps = *((const float4*)g_proj + (size_t)src * 32 + lane);
    float4 pt = *((const float4*)g_proj + (size_t)trg * 32 + lane);
    float4 vt = make_float4(ps.x * at, ps.y * at, ps.z * at, ps.w * at);
    float4 vs = make_float4(pt.x * as, pt.y * as, pt.z * as, pt.w * as);
    atomicAdd((float4*)g_acc_trg + (size_t)trg * 32 + lane, vt);
    atomicAdd((float4*)g_acc_src + (size_t)src * 32 + lane, vs);
}

// ---------------- K4: concat + LayerNorm (warp per node) -------------------
__global__ __launch_bounds__(256) void k4_layernorm(
    const float* __restrict__ gamma, const float* __restrict__ beta,
    float* __restrict__ out, int N)
{
    int n = (int)((blockIdx.x * 256 + threadIdx.x) >> 5);
    int lane = threadIdx.x & 31;
    if (n >= N) return;
    float4 a = *((const float4*)g_acc_src + (size_t)n * 32 + lane);
    float4 b = *((const float4*)g_acc_trg + (size_t)n * 32 + lane);
    float s = a.x + a.y + a.z + a.w + b.x + b.y + b.z + b.w;
    float q = a.x * a.x + a.y * a.y + a.z * a.z + a.w * a.w +
              b.x * b.x + b.y * b.y + b.z * b.z + b.w * b.w;
    #pragma unroll
    for (int mask = 16; mask >= 1; mask >>= 1) {
        s += __shfl_xor_sync(~0u, s, mask);
        q += __shfl_xor_sync(~0u, q, mask);
    }
    float mu = s * (1.f / 256.f);
    float var = q * (1.f / 256.f) - mu * mu;
    float r = rsqrtf(var + 1e-5f);
    float4 g1 = ((const float4*)gamma)[lane];
    float4 be1 = ((const float4*)beta)[lane];
    float4 g2 = ((const float4*)gamma)[32 + lane];
    float4 be2 = ((const float4*)beta)[32 + lane];
    float4 o1 = make_float4((a.x - mu) * r * g1.x + be1.x, (a.y - mu) * r * g1.y + be1.y,
                            (a.z - mu) * r * g1.z + be1.z, (a.w - mu) * r * g1.w + be1.w);
    float4 o2 = make_float4((b.x - mu) * r * g2.x + be2.x, (b.y - mu) * r * g2.y + be2.y,
                            (b.z - mu) * r * g2.z + be2.z, (b.w - mu) * r * g2.w + be2.w);
    ((float4*)out)[(size_t)n * 64 + lane] = o1;
    ((float4*)out)[(size_t)n * 64 + 32 + lane] = o2;
}

// ---------------------------------------------------------------------------
static inline int cdiv(int a, int b) { return (a + b - 1) / b; }

extern "C" void kernel_launch(void* const* d_in, const int* in_sizes, int n_in,
                              void* d_out, int out_size)
{
    const float* x      = (const float*)d_in[0];
    const int*   ei     = (const int*)d_in[1];
    const float* edges  = (const float*)d_in[2];
    const float* ins    = (const float*)d_in[3];
    const int*   bids   = (const int*)d_in[4];
    const float* Wp     = (const float*)d_in[6];
    const float* We     = (const float*)d_in[7];
    const float* Wsi    = (const float*)d_in[8];
    const float* bsi    = (const float*)d_in[9];
    const float* Wti    = (const float*)d_in[10];
    const float* bti    = (const float*)d_in[11];
    const float* Wei    = (const float*)d_in[12];
    const float* bei    = (const float*)d_in[13];
    const float* a_src  = (const float*)d_in[14];
    const float* a_trg  = (const float*)d_in[15];
    const float* a_edge = (const float*)d_in[16];
    const float* bias   = (const float*)d_in[17];
    const float* Wsk    = (const float*)d_in[18];
    const float* gamma  = (const float*)d_in[19];
    const float* beta   = (const float*)d_in[20];

    int N = in_sizes[0] / FIN_;
    int E = in_sizes[2] / EDGED_;
    int B = in_sizes[3] / HID_;
    int mle = N / B;

    const int k2_smem = H_ * EDGED_ * WAE_PAD * (int)sizeof(float);  // 66560 B
    cudaFuncSetAttribute(k2_edge_scores,
                         cudaFuncAttributeMaxDynamicSharedMemorySize, k2_smem);

    k_init<<<cdiv(N * H_, 256), 256>>>(N);
    k0_batch<<<B, 128>>>(ins, Wsi, bsi, Wti, bti, Wei, bei, a_src, a_trg, a_edge, We);
    {
        dim3 grid(cdiv(N, 128), 2);
        k1_gemm<<<grid, 256>>>(x, Wp, Wsk, bias, N, mle);
    }
    k2_edge_scores<<<296, 1024, k2_smem>>>(ei, edges, bids, E);
    k3a_exp_denom<<<cdiv(E, 256), 256>>>(ei, E);
    k3inv<<<cdiv(N * H_, 256), 256>>>(N);
    k3b_scatter<<<cdiv(E * 32, 256), 256>>>(ei, E);
    k4_layernorm<<<cdiv(N * 32, 256), 256>>>(gamma, beta, (float*)d_out, N);
}